// round 9
// baseline (speedup 1.0000x reference)
#include <cuda_runtime.h>
#include <math.h>

// Problem constants (RGCN4): fixed shapes per reference.
static constexpr int cN   = 50000;
static constexpr int cE   = 800000;
static constexpr int cR   = 3;
static constexpr int cHID = 128;
static constexpr int cD   = 384;   // = cR * 128
static constexpr int cH   = 8;
static constexpr int cL   = 4;

// ---------------- device scratch (no allocation allowed) ----------------
__device__ float g_x   [(size_t)cN * cD];          // embedding output (residual source)
__device__ float g_feat[(size_t)cN * cD];          // current node features
__device__ float g_hW  [(size_t)cR * cN * 128];    // per-relation transformed features
__device__ float g_hid [(size_t)cN * cHID];        // MLP hidden
__device__ float g_el  [(size_t)cR * cN * cH];
__device__ float g_er  [(size_t)cR * cN * cH];
__device__ float g_sum  [cHID];
__device__ float g_sumsq[cHID];
__device__ float g_scale[cHID];
__device__ float g_shift[cHID];
__device__ int   g_Mbits[cL * cR];                 // per-(layer, relation) max, monotone-int encoded
__device__ int   g_cnt   [cR * cN];
__device__ int   g_rowptr[cR * (cN + 1)];
__device__ int   g_wptr  [cR * cN];
__device__ int   g_srcs  [(size_t)cR * cE];

// ---------------- packed f32x2 helpers (Blackwell FFMA2 path) ----------------
__device__ __forceinline__ unsigned long long ffma2(unsigned long long a,
                                                    unsigned long long b,
                                                    unsigned long long c) {
    unsigned long long d;
    asm("fma.rn.f32x2 %0, %1, %2, %3;" : "=l"(d) : "l"(a), "l"(b), "l"(c));
    return d;
}
__device__ __forceinline__ unsigned long long pack_bcast(float s) {
    unsigned long long d;
    asm("mov.b64 %0, {%1, %1};" : "=l"(d) : "f"(s));
    return d;
}
__device__ __forceinline__ void unpack2(float& lo, float& hi, unsigned long long v) {
    asm("mov.b64 {%0, %1}, %2;" : "=f"(lo), "=f"(hi) : "l"(v));
}

// ---------------- monotone float<->int encoding (for atomicMax on floats) ----
__device__ __forceinline__ int fenc(float f) {
    int b = __float_as_int(f);
    return (b >= 0) ? b : ~b;        // order-preserving over all finite floats
}
__device__ __forceinline__ float fdec(int b) {
    return __int_as_float((b >= 0) ? b : ~b);
}

// ---------------- small utility kernels ----------------
__global__ void reset_stats_k() {
    int i = threadIdx.x;           // 128 threads
    g_sum[i] = 0.f; g_sumsq[i] = 0.f;
}

__global__ void zero_cnt_k() {     // also initializes all per-layer max shifts
    int i = blockIdx.x * 256 + threadIdx.x;
    if (i < cR * cN) g_cnt[i] = 0;
    if (i < cL * cR) g_Mbits[i] = fenc(-1e30f);
}

__global__ void bnfin_k(const float* __restrict__ g, const float* __restrict__ b) {
    int c = threadIdx.x;           // 128 threads
    float mu   = g_sum[c]   * (1.0f / (float)cN);
    float var  = g_sumsq[c] * (1.0f / (float)cN) - mu * mu;
    float rstd = rsqrtf(var + 1e-5f);
    float sc   = g[c] * rstd;
    g_scale[c] = sc;
    g_shift[c] = b[c] - mu * sc;
}

// ---------------- CSR build ----------------
__global__ void hist_k(const int* __restrict__ edges) {
    int idx = blockIdx.x * 256 + threadIdx.x;
    if (idx >= cR * cE) return;
    int r = idx / cE, e = idx - r * cE;
    int t = edges[(size_t)r * 2 * cE + cE + e];
    atomicAdd(&g_cnt[r * cN + t], 1);
}

// One block (1024 threads) per relation; warp-shuffle two-level scan.
__global__ void scan_k() {
    int r = blockIdx.x;
    __shared__ int warpsum[32];
    __shared__ int carry_s;
    int tid = threadIdx.x, lane = tid & 31, wd = tid >> 5;
    if (tid == 0) carry_s = 0;
    __syncthreads();
    for (int chunk = 0; chunk < cN; chunk += 1024) {
        int i = chunk + tid;
        int v = (i < cN) ? g_cnt[r * cN + i] : 0;
        // inclusive warp scan
        int x = v;
#pragma unroll
        for (int off = 1; off < 32; off <<= 1) {
            int y = __shfl_up_sync(0xffffffffu, x, off);
            if (lane >= off) x += y;
        }
        if (lane == 31) warpsum[wd] = x;
        __syncthreads();                       // B1: warpsum writes visible
        if (wd == 0) {
            int s = warpsum[lane];
#pragma unroll
            for (int off = 1; off < 32; off <<= 1) {
                int y = __shfl_up_sync(0xffffffffu, s, off);
                if (lane >= off) s += y;
            }
            warpsum[lane] = s;                 // inclusive warp-sum prefix
        }
        __syncthreads();                       // B2: scanned warpsums visible
        int warpoff = (wd > 0) ? warpsum[wd - 1] : 0;
        int excl = carry_s + warpoff + x - v;
        if (i < cN) {
            g_rowptr[r * (cN + 1) + i] = excl;
            g_wptr[r * cN + i] = excl;
        }
        __syncthreads();                       // B3: all carry_s reads done
        if (tid == 0) carry_s += warpsum[31];  // chunk total
        __syncthreads();                       // B4: carry updated before next chunk
    }
    if (tid == 0) g_rowptr[r * (cN + 1) + cN] = carry_s;
}

__global__ void scatter_k(const int* __restrict__ edges) {
    int idx = blockIdx.x * 256 + threadIdx.x;
    if (idx >= cR * cE) return;
    int r = idx / cE, e = idx - r * cE;
    int s = edges[(size_t)r * 2 * cE + e];
    int t = edges[(size_t)r * 2 * cE + cE + e];
    int p = atomicAdd(&g_wptr[r * cN + t], 1);
    g_srcs[(size_t)r * cE + p] = s;
}

// ---------------- SGEMM (BK=16, double-buffered, FFMA2 mainloop) -----------
// Each block computes a 128x128 tile of C:
//   rows row0 = blockIdx.y*128 of A (M x K, row-major, lda=K)
//   B' = B + blockIdx.x * bBlockOff  (K x ncols, row stride ldb)
//   C' = C + blockIdx.x * cBlockOff  (row stride ldc), same for C2.
// K must be a multiple of 16. ncols <= 128.
// BNRELU: A' = relu(A*scale[k]+shift[k]) applied on load (K <= 128 arrays).
// STATS:  accumulate per-column sum/sumsq of C into g_sum/g_sumsq.
// EL: requires ncols==128; computes per-row head dots with al/ar (128 floats
//     per blockIdx.x at alp + blockIdx.x*128) into elp/erp (+ blockIdx.x*cN*8).
template<bool BNRELU, bool STATS, bool EL>
__global__ __launch_bounds__(256)
void sgemm_k(const float* __restrict__ A, const float* __restrict__ B,
             float* __restrict__ C, float* __restrict__ C2,
             int M, int K, int ncols, int ldb, int ldc,
             size_t bBlockOff, size_t cBlockOff,
             const float* __restrict__ alp, const float* __restrict__ arp,
             float* __restrict__ elp, float* __restrict__ erp)
{
    __shared__ __align__(16) float As[16][132];   // row stride 528B (16B aligned)
    __shared__ __align__(16) float Bs[16][128];
    const int tid  = threadIdx.x;
    const int tx   = tid & 15;
    const int ty   = tid >> 4;
    const int row0 = blockIdx.y << 7;
    B += blockIdx.x * bBlockOff;
    C += blockIdx.x * cBlockOff;
    if (C2) C2 += blockIdx.x * cBlockOff;
    if (EL) {
        alp += blockIdx.x * 128;
        arp += blockIdx.x * 128;
        elp += (size_t)blockIdx.x * cN * cH;
        erp += (size_t)blockIdx.x * cN * cH;
    }

    // acc2[j][p] = { C[row 2p][col j], C[row 2p+1][col j] } of the 8x8 microtile
    unsigned long long acc2[8][4];
#pragma unroll
    for (int j = 0; j < 8; j++)
#pragma unroll
        for (int p = 0; p < 4; p++) acc2[j][p] = 0ull;

    // A tile load mapping: 128 rows x 16 cols; each thread: row=tid>>1, 8 cols.
    const int arow = tid >> 1;
    const int ak   = (tid & 1) << 3;          // 0 or 8
    // B tile load mapping: 16 rows x 128 cols; each thread: 2 rows (bk, bk+8), 4 cols.
    const int bk   = tid >> 5;                // 0..7
    const int bc   = (tid & 31) << 2;
    const int gr   = row0 + arow;
    const bool aval = (gr < M);
    const bool bval = (bc < ncols);

    float4 a0, a1, b0, b1;

    auto load_tile = [&](int k0) {
        a0 = make_float4(0.f, 0.f, 0.f, 0.f);
        a1 = a0; b0 = a0; b1 = a0;
        if (aval) {
            const float* ap = A + (size_t)gr * K + (k0 + ak);
            a0 = *(const float4*)(ap);
            a1 = *(const float4*)(ap + 4);
        }
        if (BNRELU) {
            int kb = k0 + ak;
            a0.x = fmaxf(fmaf(a0.x, g_scale[kb + 0], g_shift[kb + 0]), 0.f);
            a0.y = fmaxf(fmaf(a0.y, g_scale[kb + 1], g_shift[kb + 1]), 0.f);
            a0.z = fmaxf(fmaf(a0.z, g_scale[kb + 2], g_shift[kb + 2]), 0.f);
            a0.w = fmaxf(fmaf(a0.w, g_scale[kb + 3], g_shift[kb + 3]), 0.f);
            a1.x = fmaxf(fmaf(a1.x, g_scale[kb + 4], g_shift[kb + 4]), 0.f);
            a1.y = fmaxf(fmaf(a1.y, g_scale[kb + 5], g_shift[kb + 5]), 0.f);
            a1.z = fmaxf(fmaf(a1.z, g_scale[kb + 6], g_shift[kb + 6]), 0.f);
            a1.w = fmaxf(fmaf(a1.w, g_scale[kb + 7], g_shift[kb + 7]), 0.f);
        }
        if (bval) {
            b0 = *(const float4*)(B + (size_t)(k0 + bk) * ldb + bc);
            b1 = *(const float4*)(B + (size_t)(k0 + bk + 8) * ldb + bc);
        }
    };

    auto store_tile = [&]() {
        As[ak + 0][arow] = a0.x;
        As[ak + 1][arow] = a0.y;
        As[ak + 2][arow] = a0.z;
        As[ak + 3][arow] = a0.w;
        As[ak + 4][arow] = a1.x;
        As[ak + 5][arow] = a1.y;
        As[ak + 6][arow] = a1.z;
        As[ak + 7][arow] = a1.w;
        *(float4*)&Bs[bk][bc]     = b0;
        *(float4*)&Bs[bk + 8][bc] = b1;
    };

    load_tile(0);
    const int nk = K >> 4;
    for (int t = 0; t < nk; t++) {
        store_tile();
        __syncthreads();
        if (t + 1 < nk) load_tile((t + 1) << 4);   // prefetch next tile during compute
#pragma unroll
        for (int k = 0; k < 16; k++) {
            // A row pairs load directly as 64-bit packed f32x2 (contiguous, aligned)
            ulonglong2 av0 = *(const ulonglong2*)&As[k][ty * 8];
            ulonglong2 av1 = *(const ulonglong2*)&As[k][ty * 8 + 4];
            unsigned long long ap[4] = { av0.x, av0.y, av1.x, av1.y };
            float b[8];
            *(float4*)(b)     = *(const float4*)&Bs[k][tx * 8];
            *(float4*)(b + 4) = *(const float4*)&Bs[k][tx * 8 + 4];
#pragma unroll
            for (int j = 0; j < 8; j++) {
                unsigned long long bb = pack_bcast(b[j]);
#pragma unroll
                for (int p = 0; p < 4; p++)
                    acc2[j][p] = ffma2(ap[p], bb, acc2[j][p]);
            }
        }
        __syncthreads();
    }

    // ---- epilogue: unpack row pairs, store, optional stats / el-er dots ----
    float s[8], s2[8];
    if (STATS) {
#pragma unroll
        for (int j = 0; j < 8; j++) { s[j] = 0.f; s2[j] = 0.f; }
    }
    float alv[8], arv[8];
    if (EL) {
#pragma unroll
        for (int j = 0; j < 8; j++) {
            alv[j] = alp[tx * 8 + j];
            arv[j] = arp[tx * 8 + j];
        }
    }
#pragma unroll
    for (int i = 0; i < 8; i++) {
        const int p = i >> 1;
        float row[8];
#pragma unroll
        for (int j = 0; j < 8; j++) {
            float lo, hi;
            unpack2(lo, hi, acc2[j][p]);
            row[j] = (i & 1) ? hi : lo;
        }
        int r = row0 + ty * 8 + i;
        if (r < M) {
#pragma unroll
            for (int j4 = 0; j4 < 2; j4++) {
                int c = tx * 8 + j4 * 4;
                if (c < ncols) {
                    float4 v = make_float4(row[j4 * 4 + 0], row[j4 * 4 + 1],
                                           row[j4 * 4 + 2], row[j4 * 4 + 3]);
                    *(float4*)(C + (size_t)r * ldc + c) = v;
                    if (C2) *(float4*)(C2 + (size_t)r * ldc + c) = v;
                }
            }
            if (STATS) {
#pragma unroll
                for (int j = 0; j < 8; j++) { s[j] += row[j]; s2[j] += row[j] * row[j]; }
            }
        }
        if (EL) {
            // Head h = cols [h*16, h*16+16); this thread's 8 cols are half of
            // head (tx>>1). Pair-reduce with lane tx^1 (same warp, same rows).
            float pe = 0.f, pr = 0.f;
#pragma unroll
            for (int j = 0; j < 8; j++) {
                pe = fmaf(row[j], alv[j], pe);
                pr = fmaf(row[j], arv[j], pr);
            }
            pe += __shfl_xor_sync(0xffffffffu, pe, 1);
            pr += __shfl_xor_sync(0xffffffffu, pr, 1);
            if ((tx & 1) == 0 && r < M) {
                elp[(size_t)r * cH + (tx >> 1)] = pe;
                erp[(size_t)r * cH + (tx >> 1)] = pr;
            }
        }
    }
    if (STATS) {
#pragma unroll
        for (int j = 0; j < 8; j++) {
            int c = tx * 8 + j;
            if (c < ncols) {
                atomicAdd(&g_sum[c], s[j]);
                atomicAdd(&g_sumsq[c], s2[j]);
            }
        }
    }
}

// ---------------- exact global max of s per (layer, relation) ----------------
// 4 edges per thread; blocks-per-relation = ceil(cE / 1024).
__global__ void maxpass_k(const int* __restrict__ edges, int layer) {
    const int bper = (cE + 1023) / 1024;       // 782
    int r = blockIdx.x / bper;
    int e0 = (blockIdx.x % bper) * 1024 + threadIdx.x;
    const int* sp = edges + (size_t)r * 2 * cE;
    const int* tp = sp + cE;
    float m = -1e30f;
#pragma unroll
    for (int u = 0; u < 4; u++) {
        int e = e0 + u * 256;
        if (e < cE) {
            int s = sp[e], t = tp[e];
            const float4* elp = (const float4*)(g_el + ((size_t)r * cN + s) * 8);
            const float4* erp = (const float4*)(g_er + ((size_t)r * cN + t) * 8);
            float4 a0 = __ldg(elp), a1 = __ldg(elp + 1);
            float4 b0 = __ldg(erp), b1 = __ldg(erp + 1);
            float v;
            v = a0.x + b0.x; v = v >= 0.f ? v : 0.2f * v; m = fmaxf(m, v);
            v = a0.y + b0.y; v = v >= 0.f ? v : 0.2f * v; m = fmaxf(m, v);
            v = a0.z + b0.z; v = v >= 0.f ? v : 0.2f * v; m = fmaxf(m, v);
            v = a0.w + b0.w; v = v >= 0.f ? v : 0.2f * v; m = fmaxf(m, v);
            v = a1.x + b1.x; v = v >= 0.f ? v : 0.2f * v; m = fmaxf(m, v);
            v = a1.y + b1.y; v = v >= 0.f ? v : 0.2f * v; m = fmaxf(m, v);
            v = a1.z + b1.z; v = v >= 0.f ? v : 0.2f * v; m = fmaxf(m, v);
            v = a1.w + b1.w; v = v >= 0.f ? v : 0.2f * v; m = fmaxf(m, v);
        }
    }
#pragma unroll
    for (int off = 16; off; off >>= 1) m = fmaxf(m, __shfl_xor_sync(0xffffffffu, m, off));
    __shared__ float sm[8];
    if ((threadIdx.x & 31) == 0) sm[threadIdx.x >> 5] = m;
    __syncthreads();
    if (threadIdx.x < 8) {
        m = sm[threadIdx.x];
#pragma unroll
        for (int off = 4; off; off >>= 1) m = fmaxf(m, __shfl_xor_sync(0xffu, m, off));
        if (threadIdx.x == 0) atomicMax(&g_Mbits[layer * cR + r], fenc(m));
    }
}

// ---------------- GAT aggregation: one warp per (r, target-node) ----------------
// feat[n, r*128 + c] = leaky( (sum_e exp(s)*hW[src])/ (denom+1e-16), 0.01 ) + x[...]
__global__ void agg_k(int layer) {
    int gtid = blockIdx.x * blockDim.x + threadIdx.x;
    int w = gtid >> 5, lane = gtid & 31;
    if (w >= cR * cN) return;
    int r = w / cN, n = w - r * cN;
    int base = g_rowptr[r * (cN + 1) + n];
    int end  = g_rowptr[r * (cN + 1) + n + 1];
    float M = fdec(g_Mbits[layer * cR + r]);
    float erv = (lane < 8) ? g_er[((size_t)r * cN + n) * 8 + lane] : 0.f;
    const float* hWr  = g_hW + (size_t)r * cN * 128;
    const float* elr_ = g_el + (size_t)r * cN * 8;
    const int*   sp   = g_srcs + (size_t)r * cE;
    const int hsel = lane >> 2;
    float denom = 0.f;
    float4 acc = make_float4(0.f, 0.f, 0.f, 0.f);

    int i = base;
    for (; i + 1 < end; i += 2) {       // 2-way unroll: overlap the L2 gathers
        int s0 = sp[i], s1 = sp[i + 1];
        float e0 = 0.f, e1 = 0.f;
        if (lane < 8) {
            float sv0 = __ldg(elr_ + (size_t)s0 * 8 + lane) + erv;
            float sv1 = __ldg(elr_ + (size_t)s1 * 8 + lane) + erv;
            sv0 = sv0 >= 0.f ? sv0 : 0.2f * sv0;
            sv1 = sv1 >= 0.f ? sv1 : 0.2f * sv1;
            e0 = __expf(sv0 - M);
            e1 = __expf(sv1 - M);
            denom += e0 + e1;
        }
        float eh0 = __shfl_sync(0xffffffffu, e0, hsel);
        float eh1 = __shfl_sync(0xffffffffu, e1, hsel);
        float4 h0 = __ldg((const float4*)(hWr + (size_t)s0 * 128 + (lane << 2)));
        float4 h1 = __ldg((const float4*)(hWr + (size_t)s1 * 128 + (lane << 2)));
        acc.x = fmaf(eh0, h0.x, acc.x); acc.x = fmaf(eh1, h1.x, acc.x);
        acc.y = fmaf(eh0, h0.y, acc.y); acc.y = fmaf(eh1, h1.y, acc.y);
        acc.z = fmaf(eh0, h0.z, acc.z); acc.z = fmaf(eh1, h1.z, acc.z);
        acc.w = fmaf(eh0, h0.w, acc.w); acc.w = fmaf(eh1, h1.w, acc.w);
    }
    if (i < end) {
        int s0 = sp[i];
        float e0 = 0.f;
        if (lane < 8) {
            float sv0 = __ldg(elr_ + (size_t)s0 * 8 + lane) + erv;
            sv0 = sv0 >= 0.f ? sv0 : 0.2f * sv0;
            e0 = __expf(sv0 - M);
            denom += e0;
        }
        float eh0 = __shfl_sync(0xffffffffu, e0, hsel);
        float4 h0 = __ldg((const float4*)(hWr + (size_t)s0 * 128 + (lane << 2)));
        acc.x = fmaf(eh0, h0.x, acc.x);
        acc.y = fmaf(eh0, h0.y, acc.y);
        acc.z = fmaf(eh0, h0.z, acc.z);
        acc.w = fmaf(eh0, h0.w, acc.w);
    }
    float dn = __shfl_sync(0xffffffffu, denom, hsel);
    float inv = 1.f / (dn + 1e-16f);
    float4 o;
    o.x = acc.x * inv; o.y = acc.y * inv; o.z = acc.z * inv; o.w = acc.w * inv;
    o.x = o.x >= 0.f ? o.x : 0.01f * o.x;
    o.y = o.y >= 0.f ? o.y : 0.01f * o.y;
    o.z = o.z >= 0.f ? o.z : 0.01f * o.z;
    o.w = o.w >= 0.f ? o.w : 0.01f * o.w;
    size_t off = (size_t)n * cD + r * 128 + (lane << 2);
    float4 xv = *(const float4*)(g_x + off);
    o.x += xv.x; o.y += xv.y; o.z += xv.z; o.w += xv.w;
    *(float4*)(g_feat + off) = o;
}

// ---------------- launch ----------------
extern "C" void kernel_launch(void* const* d_in, const int* in_sizes, int n_in,
                              void* d_out, int out_size) {
    (void)in_sizes; (void)n_in; (void)out_size;
    const float* inputs = (const float*)d_in[0];
    const int*   edges  = (const int*)d_in[1];
    const float* W_emb1 = (const float*)d_in[2];
    const float* W_emb2 = (const float*)d_in[3];
    const float* gemb   = (const float*)d_in[4];
    const float* bemb   = (const float*)d_in[5];
    const float* Wg     = (const float*)d_in[6];
    const float* al     = (const float*)d_in[7];
    const float* ar     = (const float*)d_in[8];
    const float* W_d1   = (const float*)d_in[9];
    const float* W_d2   = (const float*)d_in[10];
    const float* gd     = (const float*)d_in[11];
    const float* bd     = (const float*)d_in[12];
    float* out = (float*)d_out;

    float *px, *pfeat, *phW, *phid, *pel, *per;
    cudaGetSymbolAddress((void**)&px,    g_x);
    cudaGetSymbolAddress((void**)&pfeat, g_feat);
    cudaGetSymbolAddress((void**)&phW,   g_hW);
    cudaGetSymbolAddress((void**)&phid,  g_hid);
    cudaGetSymbolAddress((void**)&pel,   g_el);
    cudaGetSymbolAddress((void**)&per,   g_er);

    const int rowBlocks = (cN + 127) / 128;       // 391
    const int edgeBlocks = (cR * cE + 255) / 256; // 9375
    const int maxBlocks  = cR * ((cE + 1023) / 1024); // 2346
    const int warpBlocks = (cR * cN * 32 + 255) / 256; // 18750

    // ---- CSR build (by target, per relation) + per-layer max init ----
    zero_cnt_k<<<(cR * cN + 255) / 256, 256>>>();
    hist_k<<<edgeBlocks, 256>>>(edges);
    scan_k<<<cR, 1024>>>();
    scatter_k<<<edgeBlocks, 256>>>(edges);

    // ---- embedding MLP: x = relu(BN(inputs@W1)) @ W2 ----
    reset_stats_k<<<1, 128>>>();
    sgemm_k<false, true, false><<<dim3(1, rowBlocks), 256>>>(
        inputs, W_emb1, phid, nullptr, cN, 128, 128, 128, 128, 0, 0,
        nullptr, nullptr, nullptr, nullptr);
    bnfin_k<<<1, 128>>>(gemb, bemb);
    // x-block b covers output columns b*128..b*128+127 of W_emb2 ([128, 384])
    sgemm_k<true, false, false><<<dim3(3, rowBlocks), 256>>>(
        phid, W_emb2, px, pfeat, cN, 128, 128, cD, cD, (size_t)128, (size_t)128,
        nullptr, nullptr, nullptr, nullptr);

    // ---- GAT layers (3 relation-GEMMs + el/er fused into one launch) ----
    for (int l = 0; l < cL; l++) {
        sgemm_k<false, false, true><<<dim3(3, rowBlocks), 256>>>(
            pfeat, Wg + (size_t)l * cR * cD * 128,
            phW, nullptr, cN, cD, 128, 128, 128,
            (size_t)cD * 128, (size_t)cN * 128,
            al + (size_t)l * cR * 128, ar + (size_t)l * cR * 128, pel, per);
        maxpass_k<<<maxBlocks, 256>>>(edges, l);
        agg_k<<<warpBlocks, 256>>>(l);
    }

    // ---- decoder MLP: out = relu(BN(feat@Wd1)) @ Wd2 ----
    reset_stats_k<<<1, 128>>>();
    sgemm_k<false, true, false><<<dim3(1, rowBlocks), 256>>>(
        pfeat, W_d1, phid, nullptr, cN, cD, 128, 128, 128, 0, 0,
        nullptr, nullptr, nullptr, nullptr);
    bnfin_k<<<1, 128>>>(gd, bd);
    sgemm_k<true, false, false><<<dim3(1, rowBlocks), 256>>>(
        phid, W_d2, out, nullptr, cN, 128, 64, 64, 64, 0, 0,
        nullptr, nullptr, nullptr, nullptr);
}

// round 15
// speedup vs baseline: 1.3271x; 1.3271x over previous
#include <cuda_runtime.h>
#include <math.h>

// Problem constants (RGCN4): fixed shapes per reference.
static constexpr int cN   = 50000;
static constexpr int cE   = 800000;
static constexpr int cR   = 3;
static constexpr int cHID = 128;
static constexpr int cD   = 384;   // = cR * 128
static constexpr int cH   = 8;
static constexpr int cL   = 4;

// ---------------- device scratch (no allocation allowed) ----------------
__device__ float g_x   [(size_t)cN * cD];          // embedding output (residual source)
__device__ float g_feat[(size_t)cN * cD];          // current node features
__device__ float g_hW  [(size_t)cR * cN * 128];    // per-relation transformed features
__device__ float g_hid [(size_t)cN * cHID];        // MLP hidden
__device__ float g_el  [(size_t)cR * cN * cH];
__device__ float g_er  [(size_t)cR * cN * cH];
__device__ float g_sum  [cHID];
__device__ float g_sumsq[cHID];
__device__ float g_scale[cHID];
__device__ float g_shift[cHID];
__device__ int   g_Mbits[cL * cR];                 // per-(layer, relation) max, monotone-int encoded
__device__ int   g_cnt   [cR * cN];
__device__ int   g_rowptr[cR * (cN + 1)];
__device__ int   g_wptr  [cR * cN];
__device__ int   g_srcs  [(size_t)cR * cE];

// ---------------- packed f32x2 helpers (Blackwell FFMA2 path) ----------------
__device__ __forceinline__ unsigned long long ffma2(unsigned long long a,
                                                    unsigned long long b,
                                                    unsigned long long c) {
    unsigned long long d;
    asm("fma.rn.f32x2 %0, %1, %2, %3;" : "=l"(d) : "l"(a), "l"(b), "l"(c));
    return d;
}
__device__ __forceinline__ unsigned long long pack_bcast(float s) {
    unsigned long long d;
    asm("mov.b64 %0, {%1, %1};" : "=l"(d) : "f"(s));
    return d;
}
__device__ __forceinline__ void unpack2(float& lo, float& hi, unsigned long long v) {
    asm("mov.b64 {%0, %1}, %2;" : "=f"(lo), "=f"(hi) : "l"(v));
}

// ---------------- monotone float<->int encoding (for atomicMax on floats) ----
__device__ __forceinline__ int fenc(float f) {
    int b = __float_as_int(f);
    return (b >= 0) ? b : ~b;        // order-preserving over all finite floats
}
__device__ __forceinline__ float fdec(int b) {
    return __int_as_float((b >= 0) ? b : ~b);
}

// ---------------- small utility kernels ----------------
__global__ void reset_stats_k() {
    int i = threadIdx.x;           // 128 threads
    g_sum[i] = 0.f; g_sumsq[i] = 0.f;
}

__global__ void zero_cnt_k() {     // also initializes all per-layer max shifts
    int i = blockIdx.x * 256 + threadIdx.x;
    if (i < cR * cN) g_cnt[i] = 0;
    if (i < cL * cR) g_Mbits[i] = fenc(-1e30f);
}

__global__ void bnfin_k(const float* __restrict__ g, const float* __restrict__ b) {
    int c = threadIdx.x;           // 128 threads
    float mu   = g_sum[c]   * (1.0f / (float)cN);
    float var  = g_sumsq[c] * (1.0f / (float)cN) - mu * mu;
    float rstd = rsqrtf(var + 1e-5f);
    float sc   = g[c] * rstd;
    g_scale[c] = sc;
    g_shift[c] = b[c] - mu * sc;
}

// ---------------- CSR build ----------------
__global__ void hist_k(const int* __restrict__ edges) {
    int idx = blockIdx.x * 256 + threadIdx.x;
    if (idx >= cR * cE) return;
    int r = idx / cE, e = idx - r * cE;
    int t = edges[(size_t)r * 2 * cE + cE + e];
    atomicAdd(&g_cnt[r * cN + t], 1);
}

// One block (1024 threads) per relation; warp-shuffle two-level scan.
__global__ void scan_k() {
    int r = blockIdx.x;
    __shared__ int warpsum[32];
    __shared__ int carry_s;
    int tid = threadIdx.x, lane = tid & 31, wd = tid >> 5;
    if (tid == 0) carry_s = 0;
    __syncthreads();
    for (int chunk = 0; chunk < cN; chunk += 1024) {
        int i = chunk + tid;
        int v = (i < cN) ? g_cnt[r * cN + i] : 0;
        // inclusive warp scan
        int x = v;
#pragma unroll
        for (int off = 1; off < 32; off <<= 1) {
            int y = __shfl_up_sync(0xffffffffu, x, off);
            if (lane >= off) x += y;
        }
        if (lane == 31) warpsum[wd] = x;
        __syncthreads();                       // B1: warpsum writes visible
        if (wd == 0) {
            int s = warpsum[lane];
#pragma unroll
            for (int off = 1; off < 32; off <<= 1) {
                int y = __shfl_up_sync(0xffffffffu, s, off);
                if (lane >= off) s += y;
            }
            warpsum[lane] = s;                 // inclusive warp-sum prefix
        }
        __syncthreads();                       // B2: scanned warpsums visible
        int warpoff = (wd > 0) ? warpsum[wd - 1] : 0;
        int excl = carry_s + warpoff + x - v;
        if (i < cN) {
            g_rowptr[r * (cN + 1) + i] = excl;
            g_wptr[r * cN + i] = excl;
        }
        __syncthreads();                       // B3: all carry_s reads done
        if (tid == 0) carry_s += warpsum[31];  // chunk total
        __syncthreads();                       // B4: carry updated before next chunk
    }
    if (tid == 0) g_rowptr[r * (cN + 1) + cN] = carry_s;
}

__global__ void scatter_k(const int* __restrict__ edges) {
    int idx = blockIdx.x * 256 + threadIdx.x;
    if (idx >= cR * cE) return;
    int r = idx / cE, e = idx - r * cE;
    int s = edges[(size_t)r * 2 * cE + e];
    int t = edges[(size_t)r * 2 * cE + cE + e];
    int p = atomicAdd(&g_wptr[r * cN + t], 1);
    g_srcs[(size_t)r * cE + p] = s;
}

// ---------------- SGEMM (BK=16, double-buffered, FFMA2, conflict-free B) ----
// Each block computes a 128x128 tile of C.
// Thread (tx,ty) owns rows ty*8+i and SPLIT columns {tx*4+j, tx*4+64+j} j=0..3
// (conflict-free smem B reads: 8-lane LDS.128 phase covers banks 0-31 once).
// BNRELU: A' = relu(A*scale[k]+shift[k]) on load. STATS: column sum/sumsq.
// EL (ncols==128): fused per-row head dots with al/ar into elp/erp.
// launch_bounds(256,2): cap regs at 128 so 2 CTAs/SM (16 warps) are resident —
// required to co-saturate the FFMA2 pipe and smem crossbar across the BAR.
template<bool BNRELU, bool STATS, bool EL>
__global__ __launch_bounds__(256, 2)
void sgemm_k(const float* __restrict__ A, const float* __restrict__ B,
             float* __restrict__ C, float* __restrict__ C2,
             int M, int K, int ncols, int ldb, int ldc,
             size_t bBlockOff, size_t cBlockOff,
             const float* __restrict__ alp, const float* __restrict__ arp,
             float* __restrict__ elp, float* __restrict__ erp)
{
    __shared__ __align__(16) float As[16][132];   // row stride 528B (16B aligned)
    __shared__ __align__(16) float Bs[16][128];
    const int tid  = threadIdx.x;
    const int tx   = tid & 15;
    const int ty   = tid >> 4;
    const int row0 = blockIdx.y << 7;
    B += blockIdx.x * bBlockOff;
    C += blockIdx.x * cBlockOff;
    if (C2) C2 += blockIdx.x * cBlockOff;
    if (EL) {
        alp += blockIdx.x * 128;
        arp += blockIdx.x * 128;
        elp += (size_t)blockIdx.x * cN * cH;
        erp += (size_t)blockIdx.x * cN * cH;
    }

    const int cLo = tx * 4;        // low column group base
    const int cHi = tx * 4 + 64;   // high column group base

    // acc2[j][p] = { C[row 2p][col j], C[row 2p+1][col j] }, j<4 -> cLo+j, j>=4 -> cHi+j-4
    unsigned long long acc2[8][4];
#pragma unroll
    for (int j = 0; j < 8; j++)
#pragma unroll
        for (int p = 0; p < 4; p++) acc2[j][p] = 0ull;

    // A tile load mapping: 128 rows x 16 cols; each thread: row=tid>>1, 8 cols.
    const int arow = tid >> 1;
    const int ak   = (tid & 1) << 3;          // 0 or 8
    // B tile load mapping: 16 rows x 128 cols; each thread: 2 rows (bk, bk+8), 4 cols.
    const int bk   = tid >> 5;                // 0..7
    const int bc   = (tid & 31) << 2;
    const int gr   = row0 + arow;
    const bool aval = (gr < M);
    const bool bval = (bc < ncols);

    float4 a0, a1, b0, b1;

    auto load_tile = [&](int k0) {
        a0 = make_float4(0.f, 0.f, 0.f, 0.f);
        a1 = a0; b0 = a0; b1 = a0;
        if (aval) {
            const float* ap = A + (size_t)gr * K + (k0 + ak);
            a0 = *(const float4*)(ap);
            a1 = *(const float4*)(ap + 4);
        }
        if (BNRELU) {
            int kb = k0 + ak;
            a0.x = fmaxf(fmaf(a0.x, g_scale[kb + 0], g_shift[kb + 0]), 0.f);
            a0.y = fmaxf(fmaf(a0.y, g_scale[kb + 1], g_shift[kb + 1]), 0.f);
            a0.z = fmaxf(fmaf(a0.z, g_scale[kb + 2], g_shift[kb + 2]), 0.f);
            a0.w = fmaxf(fmaf(a0.w, g_scale[kb + 3], g_shift[kb + 3]), 0.f);
            a1.x = fmaxf(fmaf(a1.x, g_scale[kb + 4], g_shift[kb + 4]), 0.f);
            a1.y = fmaxf(fmaf(a1.y, g_scale[kb + 5], g_shift[kb + 5]), 0.f);
            a1.z = fmaxf(fmaf(a1.z, g_scale[kb + 6], g_shift[kb + 6]), 0.f);
            a1.w = fmaxf(fmaf(a1.w, g_scale[kb + 7], g_shift[kb + 7]), 0.f);
        }
        if (bval) {
            b0 = *(const float4*)(B + (size_t)(k0 + bk) * ldb + bc);
            b1 = *(const float4*)(B + (size_t)(k0 + bk + 8) * ldb + bc);
        }
    };

    auto store_tile = [&]() {
        As[ak + 0][arow] = a0.x;
        As[ak + 1][arow] = a0.y;
        As[ak + 2][arow] = a0.z;
        As[ak + 3][arow] = a0.w;
        As[ak + 4][arow] = a1.x;
        As[ak + 5][arow] = a1.y;
        As[ak + 6][arow] = a1.z;
        As[ak + 7][arow] = a1.w;
        *(float4*)&Bs[bk][bc]     = b0;
        *(float4*)&Bs[bk + 8][bc] = b1;
    };

    load_tile(0);
    const int nk = K >> 4;
    for (int t = 0; t < nk; t++) {
        store_tile();
        __syncthreads();
        if (t + 1 < nk) load_tile((t + 1) << 4);   // prefetch next tile during compute
#pragma unroll
        for (int k = 0; k < 16; k++) {
            // A row pairs load directly as 64-bit packed f32x2 (broadcast, conflict-free)
            ulonglong2 av0 = *(const ulonglong2*)&As[k][ty * 8];
            ulonglong2 av1 = *(const ulonglong2*)&As[k][ty * 8 + 4];
            unsigned long long ap[4] = { av0.x, av0.y, av1.x, av1.y };
            // B fragments at tx*4 and tx*4+64: bank-conflict-free LDS.128 phases
            float b[8];
            *(float4*)(b)     = *(const float4*)&Bs[k][cLo];
            *(float4*)(b + 4) = *(const float4*)&Bs[k][cHi];
#pragma unroll
            for (int j = 0; j < 8; j++) {
                unsigned long long bb = pack_bcast(b[j]);
#pragma unroll
                for (int p = 0; p < 4; p++)
                    acc2[j][p] = ffma2(ap[p], bb, acc2[j][p]);
            }
        }
        __syncthreads();
    }

    // ---- epilogue: unpack row pairs, store, optional stats / el-er dots ----
    float s[8], s2[8];
    if (STATS) {
#pragma unroll
        for (int j = 0; j < 8; j++) { s[j] = 0.f; s2[j] = 0.f; }
    }
    float alv[8], arv[8];
    if (EL) {
#pragma unroll
        for (int j = 0; j < 8; j++) {
            int c = (j < 4) ? (cLo + j) : (cHi + j - 4);
            alv[j] = alp[c];
            arv[j] = arp[c];
        }
    }
#pragma unroll
    for (int i = 0; i < 8; i++) {
        const int p = i >> 1;
        float row[8];
#pragma unroll
        for (int j = 0; j < 8; j++) {
            float lo, hi;
            unpack2(lo, hi, acc2[j][p]);
            row[j] = (i & 1) ? hi : lo;
        }
        int r = row0 + ty * 8 + i;
        if (r < M) {
            if (cLo < ncols) {
                float4 v = make_float4(row[0], row[1], row[2], row[3]);
                *(float4*)(C + (size_t)r * ldc + cLo) = v;
                if (C2) *(float4*)(C2 + (size_t)r * ldc + cLo) = v;
            }
            if (cHi < ncols) {
                float4 v = make_float4(row[4], row[5], row[6], row[7]);
                *(float4*)(C + (size_t)r * ldc + cHi) = v;
                if (C2) *(float4*)(C2 + (size_t)r * ldc + cHi) = v;
            }
            if (STATS) {
#pragma unroll
                for (int j = 0; j < 8; j++) { s[j] += row[j]; s2[j] += row[j] * row[j]; }
            }
        }
        if (EL) {
            // Low cols form head (tx>>2); high cols form head (tx>>2)+4.
            // The 4 threads with the same tx>>2 own the head's 16 cols;
            // reduce across tx&3 via shfl_xor 1,2 (lane bits 0-1 == tx bits 0-1).
            float peL = 0.f, prL = 0.f, peH = 0.f, prH = 0.f;
#pragma unroll
            for (int j = 0; j < 4; j++) {
                peL = fmaf(row[j], alv[j], peL);
                prL = fmaf(row[j], arv[j], prL);
                peH = fmaf(row[j + 4], alv[j + 4], peH);
                prH = fmaf(row[j + 4], arv[j + 4], prH);
            }
            peL += __shfl_xor_sync(0xffffffffu, peL, 1);
            peL += __shfl_xor_sync(0xffffffffu, peL, 2);
            prL += __shfl_xor_sync(0xffffffffu, prL, 1);
            prL += __shfl_xor_sync(0xffffffffu, prL, 2);
            peH += __shfl_xor_sync(0xffffffffu, peH, 1);
            peH += __shfl_xor_sync(0xffffffffu, peH, 2);
            prH += __shfl_xor_sync(0xffffffffu, prH, 1);
            prH += __shfl_xor_sync(0xffffffffu, prH, 2);
            if ((tx & 3) == 0 && r < M) {
                int h = tx >> 2;
                elp[(size_t)r * cH + h]     = peL;
                erp[(size_t)r * cH + h]     = prL;
                elp[(size_t)r * cH + h + 4] = peH;
                erp[(size_t)r * cH + h + 4] = prH;
            }
        }
    }
    if (STATS) {
#pragma unroll
        for (int j = 0; j < 8; j++) {
            int c = (j < 4) ? (cLo + j) : (cHi + j - 4);
            if (c < ncols) {
                atomicAdd(&g_sum[c], s[j]);
                atomicAdd(&g_sumsq[c], s2[j]);
            }
        }
    }
}

// ---------------- exact global max of s per (layer, relation) ----------------
// 4 edges per thread; blocks-per-relation = ceil(cE / 1024).
__global__ void maxpass_k(const int* __restrict__ edges, int layer) {
    const int bper = (cE + 1023) / 1024;       // 782
    int r = blockIdx.x / bper;
    int e0 = (blockIdx.x % bper) * 1024 + threadIdx.x;
    const int* sp = edges + (size_t)r * 2 * cE;
    const int* tp = sp + cE;
    float m = -1e30f;
#pragma unroll
    for (int u = 0; u < 4; u++) {
        int e = e0 + u * 256;
        if (e < cE) {
            int s = sp[e], t = tp[e];
            const float4* elp = (const float4*)(g_el + ((size_t)r * cN + s) * 8);
            const float4* erp = (const float4*)(g_er + ((size_t)r * cN + t) * 8);
            float4 a0 = __ldg(elp), a1 = __ldg(elp + 1);
            float4 b0 = __ldg(erp), b1 = __ldg(erp + 1);
            float v;
            v = a0.x + b0.x; v = v >= 0.f ? v : 0.2f * v; m = fmaxf(m, v);
            v = a0.y + b0.y; v = v >= 0.f ? v : 0.2f * v; m = fmaxf(m, v);
            v = a0.z + b0.z; v = v >= 0.f ? v : 0.2f * v; m = fmaxf(m, v);
            v = a0.w + b0.w; v = v >= 0.f ? v : 0.2f * v; m = fmaxf(m, v);
            v = a1.x + b1.x; v = v >= 0.f ? v : 0.2f * v; m = fmaxf(m, v);
            v = a1.y + b1.y; v = v >= 0.f ? v : 0.2f * v; m = fmaxf(m, v);
            v = a1.z + b1.z; v = v >= 0.f ? v : 0.2f * v; m = fmaxf(m, v);
            v = a1.w + b1.w; v = v >= 0.f ? v : 0.2f * v; m = fmaxf(m, v);
        }
    }
#pragma unroll
    for (int off = 16; off; off >>= 1) m = fmaxf(m, __shfl_xor_sync(0xffffffffu, m, off));
    __shared__ float sm[8];
    if ((threadIdx.x & 31) == 0) sm[threadIdx.x >> 5] = m;
    __syncthreads();
    if (threadIdx.x < 8) {
        m = sm[threadIdx.x];
#pragma unroll
        for (int off = 4; off; off >>= 1) m = fmaxf(m, __shfl_xor_sync(0xffu, m, off));
        if (threadIdx.x == 0) atomicMax(&g_Mbits[layer * cR + r], fenc(m));
    }
}

// ---------------- GAT aggregation: one warp per (r, target-node) ----------------
// feat[n, r*128 + c] = leaky( (sum_e exp(s)*hW[src])/ (denom+1e-16), 0.01 ) + x[...]
// 4-way edge unroll: 4 independent hW gather chains in flight per warp.
__global__ void agg_k(int layer) {
    int gtid = blockIdx.x * blockDim.x + threadIdx.x;
    int w = gtid >> 5, lane = gtid & 31;
    if (w >= cR * cN) return;
    int r = w / cN, n = w - r * cN;
    int base = g_rowptr[r * (cN + 1) + n];
    int end  = g_rowptr[r * (cN + 1) + n + 1];
    float M = fdec(g_Mbits[layer * cR + r]);
    float erv = (lane < 8) ? g_er[((size_t)r * cN + n) * 8 + lane] : 0.f;
    const float* hWr  = g_hW + (size_t)r * cN * 128;
    const float* elr_ = g_el + (size_t)r * cN * 8;
    const int*   sp   = g_srcs + (size_t)r * cE;
    const int hsel = lane >> 2;
    const int co  = lane << 2;
    float denom = 0.f;
    float4 acc = make_float4(0.f, 0.f, 0.f, 0.f);

    int i = base;
    for (; i + 3 < end; i += 4) {       // 4-way unroll: 4 L2 gather chains in flight
        int s0 = sp[i], s1 = sp[i + 1], s2 = sp[i + 2], s3 = sp[i + 3];
        float e0 = 0.f, e1 = 0.f, e2 = 0.f, e3 = 0.f;
        if (lane < 8) {
            float sv0 = __ldg(elr_ + (size_t)s0 * 8 + lane) + erv;
            float sv1 = __ldg(elr_ + (size_t)s1 * 8 + lane) + erv;
            float sv2 = __ldg(elr_ + (size_t)s2 * 8 + lane) + erv;
            float sv3 = __ldg(elr_ + (size_t)s3 * 8 + lane) + erv;
            sv0 = sv0 >= 0.f ? sv0 : 0.2f * sv0;
            sv1 = sv1 >= 0.f ? sv1 : 0.2f * sv1;
            sv2 = sv2 >= 0.f ? sv2 : 0.2f * sv2;
            sv3 = sv3 >= 0.f ? sv3 : 0.2f * sv3;
            e0 = __expf(sv0 - M);
            e1 = __expf(sv1 - M);
            e2 = __expf(sv2 - M);
            e3 = __expf(sv3 - M);
            denom += (e0 + e1) + (e2 + e3);
        }
        float eh0 = __shfl_sync(0xffffffffu, e0, hsel);
        float eh1 = __shfl_sync(0xffffffffu, e1, hsel);
        float eh2 = __shfl_sync(0xffffffffu, e2, hsel);
        float eh3 = __shfl_sync(0xffffffffu, e3, hsel);
        float4 h0 = __ldg((const float4*)(hWr + (size_t)s0 * 128 + co));
        float4 h1 = __ldg((const float4*)(hWr + (size_t)s1 * 128 + co));
        float4 h2 = __ldg((const float4*)(hWr + (size_t)s2 * 128 + co));
        float4 h3 = __ldg((const float4*)(hWr + (size_t)s3 * 128 + co));
        acc.x = fmaf(eh0, h0.x, acc.x); acc.x = fmaf(eh1, h1.x, acc.x);
        acc.x = fmaf(eh2, h2.x, acc.x); acc.x = fmaf(eh3, h3.x, acc.x);
        acc.y = fmaf(eh0, h0.y, acc.y); acc.y = fmaf(eh1, h1.y, acc.y);
        acc.y = fmaf(eh2, h2.y, acc.y); acc.y = fmaf(eh3, h3.y, acc.y);
        acc.z = fmaf(eh0, h0.z, acc.z); acc.z = fmaf(eh1, h1.z, acc.z);
        acc.z = fmaf(eh2, h2.z, acc.z); acc.z = fmaf(eh3, h3.z, acc.z);
        acc.w = fmaf(eh0, h0.w, acc.w); acc.w = fmaf(eh1, h1.w, acc.w);
        acc.w = fmaf(eh2, h2.w, acc.w); acc.w = fmaf(eh3, h3.w, acc.w);
    }
    for (; i < end; i++) {              // remainder (0-3 edges)
        int s0 = sp[i];
        float e0 = 0.f;
        if (lane < 8) {
            float sv0 = __ldg(elr_ + (size_t)s0 * 8 + lane) + erv;
            sv0 = sv0 >= 0.f ? sv0 : 0.2f * sv0;
            e0 = __expf(sv0 - M);
            denom += e0;
        }
        float eh0 = __shfl_sync(0xffffffffu, e0, hsel);
        float4 h0 = __ldg((const float4*)(hWr + (size_t)s0 * 128 + co));
        acc.x = fmaf(eh0, h0.x, acc.x);
        acc.y = fmaf(eh0, h0.y, acc.y);
        acc.z = fmaf(eh0, h0.z, acc.z);
        acc.w = fmaf(eh0, h0.w, acc.w);
    }
    float dn = __shfl_sync(0xffffffffu, denom, hsel);
    float inv = 1.f / (dn + 1e-16f);
    float4 o;
    o.x = acc.x * inv; o.y = acc.y * inv; o.z = acc.z * inv; o.w = acc.w * inv;
    o.x = o.x >= 0.f ? o.x : 0.01f * o.x;
    o.y = o.y >= 0.f ? o.y : 0.01f * o.y;
    o.z = o.z >= 0.f ? o.z : 0.01f * o.z;
    o.w = o.w >= 0.f ? o.w : 0.01f * o.w;
    size_t off = (size_t)n * cD + r * 128 + co;
    float4 xv = *(const float4*)(g_x + off);
    o.x += xv.x; o.y += xv.y; o.z += xv.z; o.w += xv.w;
    *(float4*)(g_feat + off) = o;
}

// ---------------- launch ----------------
extern "C" void kernel_launch(void* const* d_in, const int* in_sizes, int n_in,
                              void* d_out, int out_size) {
    (void)in_sizes; (void)n_in; (void)out_size;
    const float* inputs = (const float*)d_in[0];
    const int*   edges  = (const int*)d_in[1];
    const float* W_emb1 = (const float*)d_in[2];
    const float* W_emb2 = (const float*)d_in[3];
    const float* gemb   = (const float*)d_in[4];
    const float* bemb   = (const float*)d_in[5];
    const float* Wg     = (const float*)d_in[6];
    const float* al     = (const float*)d_in[7];
    const float* ar     = (const float*)d_in[8];
    const float* W_d1   = (const float*)d_in[9];
    const float* W_d2   = (const float*)d_in[10];
    const float* gd     = (const float*)d_in[11];
    const float* bd     = (const float*)d_in[12];
    float* out = (float*)d_out;

    float *px, *pfeat, *phW, *phid, *pel, *per;
    cudaGetSymbolAddress((void**)&px,    g_x);
    cudaGetSymbolAddress((void**)&pfeat, g_feat);
    cudaGetSymbolAddress((void**)&phW,   g_hW);
    cudaGetSymbolAddress((void**)&phid,  g_hid);
    cudaGetSymbolAddress((void**)&pel,   g_el);
    cudaGetSymbolAddress((void**)&per,   g_er);

    const int rowBlocks = (cN + 127) / 128;       // 391
    const int edgeBlocks = (cR * cE + 255) / 256; // 9375
    const int maxBlocks  = cR * ((cE + 1023) / 1024); // 2346
    const int warpBlocks = (cR * cN * 32 + 255) / 256; // 18750

    // ---- CSR build (by target, per relation) + per-layer max init ----
    zero_cnt_k<<<(cR * cN + 255) / 256, 256>>>();
    hist_k<<<edgeBlocks, 256>>>(edges);
    scan_k<<<cR, 1024>>>();
    scatter_k<<<edgeBlocks, 256>>>(edges);

    // ---- embedding MLP: x = relu(BN(inputs@W1)) @ W2 ----
    reset_stats_k<<<1, 128>>>();
    sgemm_k<false, true, false><<<dim3(1, rowBlocks), 256>>>(
        inputs, W_emb1, phid, nullptr, cN, 128, 128, 128, 128, 0, 0,
        nullptr, nullptr, nullptr, nullptr);
    bnfin_k<<<1, 128>>>(gemb, bemb);
    // x-block b covers output columns b*128..b*128+127 of W_emb2 ([128, 384])
    sgemm_k<true, false, false><<<dim3(3, rowBlocks), 256>>>(
        phid, W_emb2, px, pfeat, cN, 128, 128, cD, cD, (size_t)128, (size_t)128,
        nullptr, nullptr, nullptr, nullptr);

    // ---- GAT layers (3 relation-GEMMs + el/er fused into one launch) ----
    for (int l = 0; l < cL; l++) {
        sgemm_k<false, false, true><<<dim3(3, rowBlocks), 256>>>(
            pfeat, Wg + (size_t)l * cR * cD * 128,
            phW, nullptr, cN, cD, 128, 128, 128,
            (size_t)cD * 128, (size_t)cN * 128,
            al + (size_t)l * cR * 128, ar + (size_t)l * cR * 128, pel, per);
        maxpass_k<<<maxBlocks, 256>>>(edges, l);
        agg_k<<<warpBlocks, 256>>>(l);
    }

    // ---- decoder MLP: out = relu(BN(feat@Wd1)) @ Wd2 ----
    reset_stats_k<<<1, 128>>>();
    sgemm_k<false, true, false><<<dim3(1, rowBlocks), 256>>>(
        pfeat, W_d1, phid, nullptr, cN, cD, 128, 128, 128, 0, 0,
        nullptr, nullptr, nullptr, nullptr);
    bnfin_k<<<1, 128>>>(gd, bd);
    sgemm_k<true, false, false><<<dim3(1, rowBlocks), 256>>>(
        phid, W_d2, out, nullptr, cN, 128, 64, 64, 64, 0, 0,
        nullptr, nullptr, nullptr, nullptr);
}